// round 15
// baseline (speedup 1.0000x reference)
#include <cuda_runtime.h>
#include <cuda_fp16.h>
#include <mma.h>
#include <math.h>

using namespace nvcuda;

#define NMAX 50000
#define NPAD (NMAX + 64)
#define EMAX 800000

// Scratch (device globals; zero-initialized, allocation-free per harness rules)
__device__ __half g_h   [NPAD * 64];   // h per layer (fp16)
__device__ __half g_x16 [NPAD * 64];   // layer-1 activations (fp16, input to gemm2)
__device__ __half g_f16 [NPAD * 128];  // features converted to fp16
__device__ __half g_wt1 [128 * 64];    // transposed W1 (fp16)
__device__ __half g_wt2 [64 * 64];     // transposed W2 (fp16)
__device__ float  g_el  [NMAX * 4];
__device__ float  g_er  [NMAX * 4];
__device__ int    g_cnt   [NMAX];
__device__ int    g_rowptr[NMAX + 1];
__device__ int    g_csr   [EMAX];

// ---------------------------------------------------------------------------
// One-shot: zero cnt, convert feat -> fp16, transpose+convert W1/W2 -> fp16.
__global__ void setupT(const float* __restrict__ feat,
                       const float* __restrict__ W1, const float* __restrict__ W2,
                       __half2* __restrict__ f16, __half* __restrict__ Wt1,
                       __half* __restrict__ Wt2, int* __restrict__ cnt, int nN)
{
    int i = blockIdx.x * blockDim.x + threadIdx.x;
    if (i < nN) cnt[i] = 0;
    int nF2 = nN * 64;                    // feat as half2 pairs (128 cols / 2)
    if (i < nF2) {
        float2 f = ((const float2*)feat)[i];
        f16[i] = __float22half2_rn(f);
    }
    if (i < 64 * 128) { int j = i >> 7, k = i & 127; Wt1[k * 64 + j] = __float2half(W1[i]); }
    if (i < 64 * 64)  { int j = i >> 6, k = i & 63;  Wt2[k * 64 + j] = __float2half(W2[i]); }
}

// CSR build: count
__global__ void csr_count(const int* __restrict__ dst, int nE, int* __restrict__ cnt) {
    int i = blockIdx.x * blockDim.x + threadIdx.x;
    if (i < nE) atomicAdd(cnt + dst[i], 1);
}

// Single-block exclusive scan of cnt -> rowptr; also re-zeroes cnt (cursor).
__global__ void __launch_bounds__(1024) csr_scan(int nN, int* __restrict__ cnt,
                                                 int* __restrict__ rowptr) {
    const int T = 1024;
    int t = threadIdx.x;
    int per = (nN + T - 1) / T;
    int start = t * per;
    int end = min(start + per, nN);
    int sum = 0;
    for (int i = start; i < end; i++) sum += cnt[i];

    __shared__ int wsum[32];
    int lane = t & 31, wid = t >> 5;
    int v = sum;
    #pragma unroll
    for (int off = 1; off < 32; off <<= 1) {
        int u = __shfl_up_sync(0xffffffffu, v, off);
        if (lane >= off) v += u;
    }
    if (lane == 31) wsum[wid] = v;
    __syncthreads();
    if (wid == 0) {
        int w = wsum[lane];
        #pragma unroll
        for (int off = 1; off < 32; off <<= 1) {
            int u = __shfl_up_sync(0xffffffffu, w, off);
            if (lane >= off) w += u;
        }
        wsum[lane] = w;
    }
    __syncthreads();
    int excl = v - sum + (wid ? wsum[wid - 1] : 0);
    int run = excl;
    for (int i = start; i < end; i++) {
        rowptr[i] = run; run += cnt[i]; cnt[i] = 0;
    }
    if (start < nN && end == nN) rowptr[nN] = run;
}

// Scatter src ids into CSR slots (cursor = re-zeroed cnt)
__global__ void csr_scatter(const int* __restrict__ src, const int* __restrict__ dst,
                            int nE, const int* __restrict__ rowptr,
                            int* __restrict__ cursor, int* __restrict__ csr) {
    int i = blockIdx.x * blockDim.x + threadIdx.x;
    if (i >= nE) return;
    int d = dst[i];
    int p = atomicAdd(cursor + d, 1);
    csr[rowptr[d] + p] = src[i];
}

// ---------------------------------------------------------------------------
// Tensor-core GEMM: Hout[n][j] = sum_k X[n][k] * Wt[k][j], X fp16 [NPAD,K],
// Wt fp16 [K,64], fp32 accum. 64x64 tile/block, 8 warps (4x2), each warp
// 16 rows x 32 cols via 2 fragments. A/B loaded straight from global (L1/L2
// cached). Epilogue: fp32 smem tile -> fp16 Hout + fused el/er projections.
template<int K>
__global__ void __launch_bounds__(256)
gemm_wmma(const __half* __restrict__ X, const __half* __restrict__ Wt,
          const float* __restrict__ al, const float* __restrict__ ar,
          __half* __restrict__ Hout, float* __restrict__ El, float* __restrict__ Er,
          int nN)
{
    __shared__ float sOut[64 * 68];
    int tid = threadIdx.x;
    int warp = tid >> 5;
    int wy = warp >> 1, wx = warp & 1;
    int base = blockIdx.x * 64;

    wmma::fragment<wmma::accumulator, 16, 16, 16, float> c0, c1;
    wmma::fill_fragment(c0, 0.f);
    wmma::fill_fragment(c1, 0.f);

    const __half* arow = X + (base + wy * 16) * K;
    #pragma unroll
    for (int k0 = 0; k0 < K; k0 += 16) {
        wmma::fragment<wmma::matrix_a, 16, 16, 16, __half, wmma::row_major> a;
        wmma::fragment<wmma::matrix_b, 16, 16, 16, __half, wmma::row_major> b0, b1;
        wmma::load_matrix_sync(a, arow + k0, K);
        wmma::load_matrix_sync(b0, Wt + k0 * 64 + wx * 32, 64);
        wmma::load_matrix_sync(b1, Wt + k0 * 64 + wx * 32 + 16, 64);
        wmma::mma_sync(c0, a, b0, c0);
        wmma::mma_sync(c1, a, b1, c1);
    }
    wmma::store_matrix_sync(sOut + (wy * 16) * 68 + wx * 32, c0, 68, wmma::mem_row_major);
    wmma::store_matrix_sync(sOut + (wy * 16) * 68 + wx * 32 + 16, c1, 68, wmma::mem_row_major);
    __syncthreads();

    // Epilogue: thread (tx,ty) covers rows 4ty..4ty+3, cols 4tx..4tx+3.
    int tx = tid & 15, ty = tid >> 4;
    int h = tx >> 2;
    float alv[4], arv[4];
    #pragma unroll
    for (int c = 0; c < 4; c++) {
        int dcol = (tx & 3) * 4 + c;
        alv[c] = al[h * 16 + dcol];
        arv[c] = ar[h * 16 + dcol];
    }

    #pragma unroll
    for (int i = 0; i < 4; i++) {
        int n = base + 4 * ty + i;
        float4 v = *(const float4*)(sOut + (4 * ty + i) * 68 + 4 * tx);
        float pl = v.x * alv[0] + v.y * alv[1] + v.z * alv[2] + v.w * alv[3];
        float pr = v.x * arv[0] + v.y * arv[1] + v.z * arv[2] + v.w * arv[3];
        #pragma unroll
        for (int off = 1; off <= 2; off <<= 1) {
            pl += __shfl_xor_sync(0xffffffffu, pl, off);
            pr += __shfl_xor_sync(0xffffffffu, pr, off);
        }
        if (n < nN) {
            union { __half2 h2[2]; uint2 u; } pk;
            pk.h2[0] = __floats2half2_rn(v.x, v.y);
            pk.h2[1] = __floats2half2_rn(v.z, v.w);
            *(uint2*)(Hout + n * 64 + 4 * tx) = pk.u;
            if ((tx & 3) == 0) {
                El[n * 4 + h] = pl;
                Er[n * 4 + h] = pr;
            }
        }
    }
}

// ---------------------------------------------------------------------------
// Gather aggregation — simple 1-edge loop (batched variants regressed twice:
// front-batched gathers inflate MLP_p1 -> cross-CTA L1tex-queue spread).
// fp16 h rows: 64 halfs = 16 uint2 per row; lane l owns uint2 #l.
// Logits tiny by construction -> unshifted softmax. fp32 accumulation.
// MODE 0: relu(out+b) -> X16 (fp16, feeds gemm2). MODE 1: mean-head + log_softmax.
template<int MODE>
__global__ void __launch_bounds__(256)
aggregate(int nN, const int* __restrict__ rowptr, const int* __restrict__ csr,
          const float* __restrict__ el, const float* __restrict__ er,
          const __half* __restrict__ hfeat, const float* __restrict__ b,
          float* __restrict__ outf, __half* __restrict__ outh)
{
    int tid = threadIdx.x;
    int n = blockIdx.x * 16 + (tid >> 4);
    bool valid = (n < nN);
    int nc = valid ? n : (nN - 1);
    int l = tid & 15;
    int head = l >> 2;

    float erv = er[4 * nc + head];
    int p = rowptr[nc], pe = rowptr[nc + 1];

    float s = 0.f;
    float4 acc = make_float4(0.f, 0.f, 0.f, 0.f);
    const uint2* hf = (const uint2*)hfeat;   // 16 uint2 per 64-half row

    while (p < pe) {
        int sn = csr[p];
        float e = el[4 * sn + head] + erv;
        uint2 u = hf[sn * 16 + l];
        e = (e > 0.f) ? e : 0.2f * e;
        float a = __expf(e);
        union { uint2 u; __half2 h2[2]; } pk; pk.u = u;
        float2 f01 = __half22float2(pk.h2[0]);
        float2 f23 = __half22float2(pk.h2[1]);
        s += a;
        acc.x = fmaf(a, f01.x, acc.x);
        acc.y = fmaf(a, f01.y, acc.y);
        acc.z = fmaf(a, f23.x, acc.z);
        acc.w = fmaf(a, f23.y, acc.w);
        p++;
    }

    float inv = (s > 0.f) ? 1.f / s : 0.f;
    int j0 = 4 * l;
    float v0 = fmaf(acc.x, inv, b[j0 + 0]);
    float v1 = fmaf(acc.y, inv, b[j0 + 1]);
    float v2 = fmaf(acc.z, inv, b[j0 + 2]);
    float v3 = fmaf(acc.w, inv, b[j0 + 3]);

    if (MODE == 0) {
        if (valid) {
            union { __half2 h2[2]; uint2 u; } pk;
            pk.h2[0] = __floats2half2_rn(fmaxf(v0, 0.f), fmaxf(v1, 0.f));
            pk.h2[1] = __floats2half2_rn(fmaxf(v2, 0.f), fmaxf(v3, 0.f));
            *(uint2*)(outh + 64 * n + j0) = pk.u;
        }
    } else {
        // sum over heads: lanes differing in bits 2,3 hold same class range
        #pragma unroll
        for (int off = 4; off <= 8; off <<= 1) {
            v0 += __shfl_xor_sync(0xffffffffu, v0, off);
            v1 += __shfl_xor_sync(0xffffffffu, v1, off);
            v2 += __shfl_xor_sync(0xffffffffu, v2, off);
            v3 += __shfl_xor_sync(0xffffffffu, v3, off);
        }
        v0 *= 0.25f; v1 *= 0.25f; v2 *= 0.25f; v3 *= 0.25f;
        // log-softmax over 16 classes: lanes 0..3 (and replicas) hold them
        float mx = fmaxf(fmaxf(v0, v1), fmaxf(v2, v3));
        #pragma unroll
        for (int off = 1; off <= 2; off <<= 1)
            mx = fmaxf(mx, __shfl_xor_sync(0xffffffffu, mx, off));
        float se = expf(v0 - mx) + expf(v1 - mx) + expf(v2 - mx) + expf(v3 - mx);
        #pragma unroll
        for (int off = 1; off <= 2; off <<= 1)
            se += __shfl_xor_sync(0xffffffffu, se, off);
        float lse = mx + logf(se);
        if (valid && l < 4) {
            float4 o = make_float4(v0 - lse, v1 - lse, v2 - lse, v3 - lse);
            *(float4*)(outf + 16 * n + j0) = o;
        }
    }
}

// ---------------------------------------------------------------------------
extern "C" void kernel_launch(void* const* d_in, const int* in_sizes, int n_in,
                              void* d_out, int out_size)
{
    const float* feat = (const float*)d_in[0];
    const int*   src  = (const int*)d_in[1];
    const int*   dst  = (const int*)d_in[2];
    const float* W1   = (const float*)d_in[3];
    const float* al1  = (const float*)d_in[4];
    const float* ar1  = (const float*)d_in[5];
    const float* b1   = (const float*)d_in[6];
    const float* W2   = (const float*)d_in[7];
    const float* al2  = (const float*)d_in[8];
    const float* ar2  = (const float*)d_in[9];
    const float* b2   = (const float*)d_in[10];
    float* out = (float*)d_out;

    int nN = in_sizes[0] / 128;
    int nE = in_sizes[1];

    __half *p_h, *p_x16, *p_f16, *p_wt1, *p_wt2;
    float *p_el, *p_er;
    int *p_cnt, *p_rowptr, *p_csr;
    cudaGetSymbolAddress((void**)&p_h,     g_h);
    cudaGetSymbolAddress((void**)&p_x16,   g_x16);
    cudaGetSymbolAddress((void**)&p_f16,   g_f16);
    cudaGetSymbolAddress((void**)&p_wt1,   g_wt1);
    cudaGetSymbolAddress((void**)&p_wt2,   g_wt2);
    cudaGetSymbolAddress((void**)&p_el,    g_el);
    cudaGetSymbolAddress((void**)&p_er,    g_er);
    cudaGetSymbolAddress((void**)&p_cnt,   g_cnt);
    cudaGetSymbolAddress((void**)&p_rowptr,g_rowptr);
    cudaGetSymbolAddress((void**)&p_csr,   g_csr);

    const int TB = 256;
    int gEdge  = (nE + TB - 1) / TB;
    int gGemm  = (nN + 63) / 64;
    int gAgg   = (nN + 15) / 16;
    int gSetup = (nN * 64 + TB - 1) / TB;   // covers feat half2 count (largest)

    // Ordered so gemm_wmma<128> sits in the ncu -s 5 capture slot.
    setupT<<<gSetup, TB>>>(feat, W1, W2, (__half2*)p_f16, p_wt1, p_wt2, p_cnt, nN); // 0
    csr_count<<<gEdge, TB>>>(dst, nE, p_cnt);                                       // 1
    csr_scan<<<1, 1024>>>(nN, p_cnt, p_rowptr);                                     // 2
    gemm_wmma<128><<<gGemm, TB>>>(p_f16, p_wt1, al1, ar1, p_h, p_el, p_er, nN);     // 3
    csr_scatter<<<gEdge, TB>>>(src, dst, nE, p_rowptr, p_cnt, p_csr);               // 4

    aggregate<0><<<gAgg, TB>>>(nN, p_rowptr, p_csr, p_el, p_er, p_h, b1,
                               nullptr, p_x16);                                     // 5

    gemm_wmma<64><<<gGemm, TB>>>(p_x16, p_wt2, al2, ar2, p_h, p_el, p_er, nN);      // 6
    aggregate<1><<<gAgg, TB>>>(nN, p_rowptr, p_csr, p_el, p_er, p_h, b2,
                               out, nullptr);                                       // 7
}

// round 16
// speedup vs baseline: 1.1463x; 1.1463x over previous
#include <cuda_runtime.h>
#include <cuda_fp16.h>
#include <mma.h>
#include <math.h>

using namespace nvcuda;

#define NMAX 50000
#define NPAD (NMAX + 64)
#define EMAX 800000

// Scratch (device globals; zero-initialized, allocation-free per harness rules)
__device__ __half g_h   [NPAD * 64];   // h per layer (fp16)
__device__ __half g_x16 [NPAD * 64];   // layer-1 activations (fp16, input to gemm2)
__device__ __half g_f16 [NPAD * 128];  // features converted to fp16
__device__ __half g_wt1 [128 * 64];    // transposed W1 (fp16)
__device__ __half g_wt2 [64 * 64];     // transposed W2 (fp16)
__device__ float  g_el  [NMAX * 4];
__device__ float  g_er  [NMAX * 4];
__device__ int    g_cnt   [NMAX];
__device__ int    g_rowptr[NMAX + 1];
__device__ int    g_csr   [EMAX];

// ---------------------------------------------------------------------------
// One-shot: zero cnt, convert feat -> fp16, transpose+convert W1/W2 -> fp16.
__global__ void setupT(const float* __restrict__ feat,
                       const float* __restrict__ W1, const float* __restrict__ W2,
                       __half2* __restrict__ f16, __half* __restrict__ Wt1,
                       __half* __restrict__ Wt2, int* __restrict__ cnt, int nN)
{
    int i = blockIdx.x * blockDim.x + threadIdx.x;
    if (i < nN) cnt[i] = 0;
    int nF2 = nN * 64;                    // feat as half2 pairs (128 cols / 2)
    if (i < nF2) {
        float2 f = ((const float2*)feat)[i];
        f16[i] = __float22half2_rn(f);
    }
    if (i < 64 * 128) { int j = i >> 7, k = i & 127; Wt1[k * 64 + j] = __float2half(W1[i]); }
    if (i < 64 * 64)  { int j = i >> 6, k = i & 63;  Wt2[k * 64 + j] = __float2half(W2[i]); }
}

// CSR build: count
__global__ void csr_count(const int* __restrict__ dst, int nE, int* __restrict__ cnt) {
    int i = blockIdx.x * blockDim.x + threadIdx.x;
    if (i < nE) atomicAdd(cnt + dst[i], 1);
}

// Single-block exclusive scan of cnt -> rowptr; also re-zeroes cnt (cursor).
__global__ void __launch_bounds__(1024) csr_scan(int nN, int* __restrict__ cnt,
                                                 int* __restrict__ rowptr) {
    const int T = 1024;
    int t = threadIdx.x;
    int per = (nN + T - 1) / T;
    int start = t * per;
    int end = min(start + per, nN);
    int sum = 0;
    for (int i = start; i < end; i++) sum += cnt[i];

    __shared__ int wsum[32];
    int lane = t & 31, wid = t >> 5;
    int v = sum;
    #pragma unroll
    for (int off = 1; off < 32; off <<= 1) {
        int u = __shfl_up_sync(0xffffffffu, v, off);
        if (lane >= off) v += u;
    }
    if (lane == 31) wsum[wid] = v;
    __syncthreads();
    if (wid == 0) {
        int w = wsum[lane];
        #pragma unroll
        for (int off = 1; off < 32; off <<= 1) {
            int u = __shfl_up_sync(0xffffffffu, w, off);
            if (lane >= off) w += u;
        }
        wsum[lane] = w;
    }
    __syncthreads();
    int excl = v - sum + (wid ? wsum[wid - 1] : 0);
    int run = excl;
    for (int i = start; i < end; i++) {
        rowptr[i] = run; run += cnt[i]; cnt[i] = 0;
    }
    if (start < nN && end == nN) rowptr[nN] = run;
}

// Scatter src ids into CSR slots (cursor = re-zeroed cnt)
__global__ void csr_scatter(const int* __restrict__ src, const int* __restrict__ dst,
                            int nE, const int* __restrict__ rowptr,
                            int* __restrict__ cursor, int* __restrict__ csr) {
    int i = blockIdx.x * blockDim.x + threadIdx.x;
    if (i >= nE) return;
    int d = dst[i];
    int p = atomicAdd(cursor + d, 1);
    csr[rowptr[d] + p] = src[i];
}

// ---------------------------------------------------------------------------
// Tensor-core GEMM with smem-staged operands. 64x64 tile/block, 8 warps (4x2),
// each warp 16x32 via 2 acc fragments. A tile [64,K] and B tile [K,64] staged
// once (padded lds: A=K+8 halfs, B=72 halfs -> 16B-aligned LDSM, low conflict).
// fp32 epilogue tile aliases the A/B smem region (sync-fenced).
template<int K>
__global__ void __launch_bounds__(256)
gemm_wmma(const __half* __restrict__ X, const __half* __restrict__ Wt,
          const float* __restrict__ al, const float* __restrict__ ar,
          __half* __restrict__ Hout, float* __restrict__ El, float* __restrict__ Er,
          int nN)
{
    constexpr int LDA = K + 8;            // halfs per A smem row
    constexpr int LDB = 72;               // halfs per B smem row
    constexpr int A_BYTES = 64 * LDA * 2;
    constexpr int B_BYTES = K * LDB * 2;
    __shared__ __align__(16) char smem_raw[A_BYTES + B_BYTES];
    __half* sA = (__half*)smem_raw;
    __half* sB = (__half*)(smem_raw + A_BYTES);
    float* sOut = (float*)smem_raw;       // aliases sA/sB after mma (fenced)

    int tid = threadIdx.x;
    int warp = tid >> 5;
    int wy = warp >> 1, wx = warp & 1;
    int base = blockIdx.x * 64;

    // Stage A: 64 rows x K halfs, uint4 = 8 halfs per chunk, coalesced.
    {
        const uint4* src4 = (const uint4*)(X + (size_t)base * K);
        constexpr int CHUNKS = 64 * K / 8;
        #pragma unroll
        for (int c = tid; c < CHUNKS; c += 256) {
            int row = c / (K / 8), col8 = c % (K / 8);
            *(uint4*)(sA + row * LDA + col8 * 8) = src4[c];
        }
    }
    // Stage B: K rows x 64 halfs.
    {
        const uint4* src4 = (const uint4*)Wt;
        constexpr int CHUNKS = K * 64 / 8;
        #pragma unroll
        for (int c = tid; c < CHUNKS; c += 256) {
            int row = c / 8, col8 = c % 8;
            *(uint4*)(sB + row * LDB + col8 * 8) = src4[c];
        }
    }
    __syncthreads();

    wmma::fragment<wmma::accumulator, 16, 16, 16, float> c0, c1;
    wmma::fill_fragment(c0, 0.f);
    wmma::fill_fragment(c1, 0.f);

    #pragma unroll
    for (int k0 = 0; k0 < K; k0 += 16) {
        wmma::fragment<wmma::matrix_a, 16, 16, 16, __half, wmma::row_major> a;
        wmma::fragment<wmma::matrix_b, 16, 16, 16, __half, wmma::row_major> b0, b1;
        wmma::load_matrix_sync(a, sA + (wy * 16) * LDA + k0, LDA);
        wmma::load_matrix_sync(b0, sB + k0 * LDB + wx * 32, LDB);
        wmma::load_matrix_sync(b1, sB + k0 * LDB + wx * 32 + 16, LDB);
        wmma::mma_sync(c0, a, b0, c0);
        wmma::mma_sync(c1, a, b1, c1);
    }
    __syncthreads();                      // all reads of sA/sB done
    wmma::store_matrix_sync(sOut + (wy * 16) * 68 + wx * 32, c0, 68, wmma::mem_row_major);
    wmma::store_matrix_sync(sOut + (wy * 16) * 68 + wx * 32 + 16, c1, 68, wmma::mem_row_major);
    __syncthreads();

    // Epilogue: thread (tx,ty) covers rows 4ty..4ty+3, cols 4tx..4tx+3.
    int tx = tid & 15, ty = tid >> 4;
    int h = tx >> 2;
    float alv[4], arv[4];
    #pragma unroll
    for (int c = 0; c < 4; c++) {
        int dcol = (tx & 3) * 4 + c;
        alv[c] = al[h * 16 + dcol];
        arv[c] = ar[h * 16 + dcol];
    }

    #pragma unroll
    for (int i = 0; i < 4; i++) {
        int n = base + 4 * ty + i;
        float4 v = *(const float4*)(sOut + (4 * ty + i) * 68 + 4 * tx);
        float pl = v.x * alv[0] + v.y * alv[1] + v.z * alv[2] + v.w * alv[3];
        float pr = v.x * arv[0] + v.y * arv[1] + v.z * arv[2] + v.w * arv[3];
        #pragma unroll
        for (int off = 1; off <= 2; off <<= 1) {
            pl += __shfl_xor_sync(0xffffffffu, pl, off);
            pr += __shfl_xor_sync(0xffffffffu, pr, off);
        }
        if (n < nN) {
            union { __half2 h2[2]; uint2 u; } pk;
            pk.h2[0] = __floats2half2_rn(v.x, v.y);
            pk.h2[1] = __floats2half2_rn(v.z, v.w);
            *(uint2*)(Hout + n * 64 + 4 * tx) = pk.u;
            if ((tx & 3) == 0) {
                El[n * 4 + h] = pl;
                Er[n * 4 + h] = pr;
            }
        }
    }
}

// ---------------------------------------------------------------------------
// Gather aggregation — simple 1-edge loop (batched variants regressed twice:
// front-batched gathers inflate MLP_p1 -> cross-CTA L1tex-queue spread).
// fp16 h rows: 64 halfs = 16 uint2 per row; lane l owns uint2 #l.
// Logits tiny by construction -> unshifted softmax. fp32 accumulation.
// MODE 0: relu(out+b) -> X16 (fp16, feeds gemm2). MODE 1: mean-head + log_softmax.
template<int MODE>
__global__ void __launch_bounds__(256)
aggregate(int nN, const int* __restrict__ rowptr, const int* __restrict__ csr,
          const float* __restrict__ el, const float* __restrict__ er,
          const __half* __restrict__ hfeat, const float* __restrict__ b,
          float* __restrict__ outf, __half* __restrict__ outh)
{
    int tid = threadIdx.x;
    int n = blockIdx.x * 16 + (tid >> 4);
    bool valid = (n < nN);
    int nc = valid ? n : (nN - 1);
    int l = tid & 15;
    int head = l >> 2;

    float erv = er[4 * nc + head];
    int p = rowptr[nc], pe = rowptr[nc + 1];

    float s = 0.f;
    float4 acc = make_float4(0.f, 0.f, 0.f, 0.f);
    const uint2* hf = (const uint2*)hfeat;   // 16 uint2 per 64-half row

    while (p < pe) {
        int sn = csr[p];
        float e = el[4 * sn + head] + erv;
        uint2 u = hf[sn * 16 + l];
        e = (e > 0.f) ? e : 0.2f * e;
        float a = __expf(e);
        union { uint2 u; __half2 h2[2]; } pk; pk.u = u;
        float2 f01 = __half22float2(pk.h2[0]);
        float2 f23 = __half22float2(pk.h2[1]);
        s += a;
        acc.x = fmaf(a, f01.x, acc.x);
        acc.y = fmaf(a, f01.y, acc.y);
        acc.z = fmaf(a, f23.x, acc.z);
        acc.w = fmaf(a, f23.y, acc.w);
        p++;
    }

    float inv = (s > 0.f) ? 1.f / s : 0.f;
    int j0 = 4 * l;
    float v0 = fmaf(acc.x, inv, b[j0 + 0]);
    float v1 = fmaf(acc.y, inv, b[j0 + 1]);
    float v2 = fmaf(acc.z, inv, b[j0 + 2]);
    float v3 = fmaf(acc.w, inv, b[j0 + 3]);

    if (MODE == 0) {
        if (valid) {
            union { __half2 h2[2]; uint2 u; } pk;
            pk.h2[0] = __floats2half2_rn(fmaxf(v0, 0.f), fmaxf(v1, 0.f));
            pk.h2[1] = __floats2half2_rn(fmaxf(v2, 0.f), fmaxf(v3, 0.f));
            *(uint2*)(outh + 64 * n + j0) = pk.u;
        }
    } else {
        // sum over heads: lanes differing in bits 2,3 hold same class range
        #pragma unroll
        for (int off = 4; off <= 8; off <<= 1) {
            v0 += __shfl_xor_sync(0xffffffffu, v0, off);
            v1 += __shfl_xor_sync(0xffffffffu, v1, off);
            v2 += __shfl_xor_sync(0xffffffffu, v2, off);
            v3 += __shfl_xor_sync(0xffffffffu, v3, off);
        }
        v0 *= 0.25f; v1 *= 0.25f; v2 *= 0.25f; v3 *= 0.25f;
        // log-softmax over 16 classes: lanes 0..3 (and replicas) hold them
        float mx = fmaxf(fmaxf(v0, v1), fmaxf(v2, v3));
        #pragma unroll
        for (int off = 1; off <= 2; off <<= 1)
            mx = fmaxf(mx, __shfl_xor_sync(0xffffffffu, mx, off));
        float se = expf(v0 - mx) + expf(v1 - mx) + expf(v2 - mx) + expf(v3 - mx);
        #pragma unroll
        for (int off = 1; off <= 2; off <<= 1)
            se += __shfl_xor_sync(0xffffffffu, se, off);
        float lse = mx + logf(se);
        if (valid && l < 4) {
            float4 o = make_float4(v0 - lse, v1 - lse, v2 - lse, v3 - lse);
            *(float4*)(outf + 16 * n + j0) = o;
        }
    }
}

// ---------------------------------------------------------------------------
extern "C" void kernel_launch(void* const* d_in, const int* in_sizes, int n_in,
                              void* d_out, int out_size)
{
    const float* feat = (const float*)d_in[0];
    const int*   src  = (const int*)d_in[1];
    const int*   dst  = (const int*)d_in[2];
    const float* W1   = (const float*)d_in[3];
    const float* al1  = (const float*)d_in[4];
    const float* ar1  = (const float*)d_in[5];
    const float* b1   = (const float*)d_in[6];
    const float* W2   = (const float*)d_in[7];
    const float* al2  = (const float*)d_in[8];
    const float* ar2  = (const float*)d_in[9];
    const float* b2   = (const float*)d_in[10];
    float* out = (float*)d_out;

    int nN = in_sizes[0] / 128;
    int nE = in_sizes[1];

    __half *p_h, *p_x16, *p_f16, *p_wt1, *p_wt2;
    float *p_el, *p_er;
    int *p_cnt, *p_rowptr, *p_csr;
    cudaGetSymbolAddress((void**)&p_h,     g_h);
    cudaGetSymbolAddress((void**)&p_x16,   g_x16);
    cudaGetSymbolAddress((void**)&p_f16,   g_f16);
    cudaGetSymbolAddress((void**)&p_wt1,   g_wt1);
    cudaGetSymbolAddress((void**)&p_wt2,   g_wt2);
    cudaGetSymbolAddress((void**)&p_el,    g_el);
    cudaGetSymbolAddress((void**)&p_er,    g_er);
    cudaGetSymbolAddress((void**)&p_cnt,   g_cnt);
    cudaGetSymbolAddress((void**)&p_rowptr,g_rowptr);
    cudaGetSymbolAddress((void**)&p_csr,   g_csr);

    const int TB = 256;
    int gEdge  = (nE + TB - 1) / TB;
    int gGemm  = (nN + 63) / 64;
    int gAgg   = (nN + 15) / 16;
    int gSetup = (nN * 64 + TB - 1) / TB;   // covers feat half2 count (largest)

    // Ordered so gemm_wmma<128> sits in the ncu -s 5 capture slot.
    setupT<<<gSetup, TB>>>(feat, W1, W2, (__half2*)p_f16, p_wt1, p_wt2, p_cnt, nN); // 0
    csr_count<<<gEdge, TB>>>(dst, nE, p_cnt);                                       // 1
    csr_scan<<<1, 1024>>>(nN, p_cnt, p_rowptr);                                     // 2
    gemm_wmma<128><<<gGemm, TB>>>(p_f16, p_wt1, al1, ar1, p_h, p_el, p_er, nN);     // 3
    csr_scatter<<<gEdge, TB>>>(src, dst, nE, p_rowptr, p_cnt, p_csr);               // 4

    aggregate<0><<<gAgg, TB>>>(nN, p_rowptr, p_csr, p_el, p_er, p_h, b1,
                               nullptr, p_x16);                                     // 5

    gemm_wmma<64><<<gGemm, TB>>>(p_x16, p_wt2, al2, ar2, p_h, p_el, p_er, nN);      // 6
    aggregate<1><<<gAgg, TB>>>(nN, p_rowptr, p_csr, p_el, p_er, p_h, b2,
                               out, nullptr);                                       // 7
}

// round 17
// speedup vs baseline: 1.2015x; 1.0482x over previous
#include <cuda_runtime.h>
#include <cuda_fp16.h>
#include <mma.h>
#include <math.h>

using namespace nvcuda;

#define NMAX 50000
#define NPAD (NMAX + 64)
#define EMAX 800000

// Scratch (device globals; zero-initialized, allocation-free per harness rules)
__device__ __half g_h   [NPAD * 64];   // h per layer (fp16)
__device__ __half g_x16 [NPAD * 64];   // layer-1 activations (fp16, input to gemm2)
__device__ __half g_f16 [NPAD * 128];  // features converted to fp16
__device__ __half g_wt1 [128 * 64];    // transposed W1 (fp16)
__device__ __half g_wt2 [64 * 64];     // transposed W2 (fp16)
__device__ float  g_el  [NMAX * 4];
__device__ float  g_er  [NMAX * 4];
__device__ int    g_cnt   [NMAX];
__device__ int    g_rowptr[NMAX + 1];
__device__ int    g_csr   [EMAX];

// ---------------------------------------------------------------------------
// One-shot: zero cnt, convert feat -> fp16, transpose+convert W1/W2 -> fp16.
__global__ void setupT(const float* __restrict__ feat,
                       const float* __restrict__ W1, const float* __restrict__ W2,
                       __half2* __restrict__ f16, __half* __restrict__ Wt1,
                       __half* __restrict__ Wt2, int* __restrict__ cnt, int nN)
{
    int i = blockIdx.x * blockDim.x + threadIdx.x;
    if (i < nN) cnt[i] = 0;
    int nF2 = nN * 64;                    // feat as half2 pairs (128 cols / 2)
    if (i < nF2) {
        float2 f = ((const float2*)feat)[i];
        f16[i] = __float22half2_rn(f);
    }
    if (i < 64 * 128) { int j = i >> 7, k = i & 127; Wt1[k * 64 + j] = __float2half(W1[i]); }
    if (i < 64 * 64)  { int j = i >> 6, k = i & 63;  Wt2[k * 64 + j] = __float2half(W2[i]); }
}

// CSR build: count
__global__ void csr_count(const int* __restrict__ dst, int nE, int* __restrict__ cnt) {
    int i = blockIdx.x * blockDim.x + threadIdx.x;
    if (i < nE) atomicAdd(cnt + dst[i], 1);
}

// Single-block exclusive scan of cnt -> rowptr; also re-zeroes cnt (cursor).
__global__ void __launch_bounds__(1024) csr_scan(int nN, int* __restrict__ cnt,
                                                 int* __restrict__ rowptr) {
    const int T = 1024;
    int t = threadIdx.x;
    int per = (nN + T - 1) / T;
    int start = t * per;
    int end = min(start + per, nN);
    int sum = 0;
    for (int i = start; i < end; i++) sum += cnt[i];

    __shared__ int wsum[32];
    int lane = t & 31, wid = t >> 5;
    int v = sum;
    #pragma unroll
    for (int off = 1; off < 32; off <<= 1) {
        int u = __shfl_up_sync(0xffffffffu, v, off);
        if (lane >= off) v += u;
    }
    if (lane == 31) wsum[wid] = v;
    __syncthreads();
    if (wid == 0) {
        int w = wsum[lane];
        #pragma unroll
        for (int off = 1; off < 32; off <<= 1) {
            int u = __shfl_up_sync(0xffffffffu, w, off);
            if (lane >= off) w += u;
        }
        wsum[lane] = w;
    }
    __syncthreads();
    int excl = v - sum + (wid ? wsum[wid - 1] : 0);
    int run = excl;
    for (int i = start; i < end; i++) {
        rowptr[i] = run; run += cnt[i]; cnt[i] = 0;
    }
    if (start < nN && end == nN) rowptr[nN] = run;
}

// Scatter src ids into CSR slots (cursor = re-zeroed cnt)
__global__ void csr_scatter(const int* __restrict__ src, const int* __restrict__ dst,
                            int nE, const int* __restrict__ rowptr,
                            int* __restrict__ cursor, int* __restrict__ csr) {
    int i = blockIdx.x * blockDim.x + threadIdx.x;
    if (i >= nE) return;
    int d = dst[i];
    int p = atomicAdd(cursor + d, 1);
    csr[rowptr[d] + p] = src[i];
}

// ---------------------------------------------------------------------------
// Tensor-core GEMM with smem-staged operands. 64x64 tile/block, 8 warps (4x2),
// each warp 16x32 via 2 acc fragments. A tile [64,K] and B tile [K,64] staged
// once (padded lds: A=K+8 halfs, B=72 halfs -> 16B-aligned LDSM, low conflict).
// fp32 epilogue tile aliases the A/B smem region (sync-fenced).
template<int K>
__global__ void __launch_bounds__(256)
gemm_wmma(const __half* __restrict__ X, const __half* __restrict__ Wt,
          const float* __restrict__ al, const float* __restrict__ ar,
          __half* __restrict__ Hout, float* __restrict__ El, float* __restrict__ Er,
          int nN)
{
    constexpr int LDA = K + 8;            // halfs per A smem row
    constexpr int LDB = 72;               // halfs per B smem row
    constexpr int A_BYTES = 64 * LDA * 2;
    constexpr int B_BYTES = K * LDB * 2;
    __shared__ __align__(16) char smem_raw[A_BYTES + B_BYTES];
    __half* sA = (__half*)smem_raw;
    __half* sB = (__half*)(smem_raw + A_BYTES);
    float* sOut = (float*)smem_raw;       // aliases sA/sB after mma (fenced)

    int tid = threadIdx.x;
    int warp = tid >> 5;
    int wy = warp >> 1, wx = warp & 1;
    int base = blockIdx.x * 64;

    // Stage A: 64 rows x K halfs, uint4 = 8 halfs per chunk, coalesced.
    {
        const uint4* src4 = (const uint4*)(X + (size_t)base * K);
        constexpr int CHUNKS = 64 * K / 8;
        #pragma unroll
        for (int c = tid; c < CHUNKS; c += 256) {
            int row = c / (K / 8), col8 = c % (K / 8);
            *(uint4*)(sA + row * LDA + col8 * 8) = src4[c];
        }
    }
    // Stage B: K rows x 64 halfs.
    {
        const uint4* src4 = (const uint4*)Wt;
        constexpr int CHUNKS = K * 64 / 8;
        #pragma unroll
        for (int c = tid; c < CHUNKS; c += 256) {
            int row = c / 8, col8 = c % 8;
            *(uint4*)(sB + row * LDB + col8 * 8) = src4[c];
        }
    }
    __syncthreads();

    wmma::fragment<wmma::accumulator, 16, 16, 16, float> c0, c1;
    wmma::fill_fragment(c0, 0.f);
    wmma::fill_fragment(c1, 0.f);

    #pragma unroll
    for (int k0 = 0; k0 < K; k0 += 16) {
        wmma::fragment<wmma::matrix_a, 16, 16, 16, __half, wmma::row_major> a;
        wmma::fragment<wmma::matrix_b, 16, 16, 16, __half, wmma::row_major> b0, b1;
        wmma::load_matrix_sync(a, sA + (wy * 16) * LDA + k0, LDA);
        wmma::load_matrix_sync(b0, sB + k0 * LDB + wx * 32, LDB);
        wmma::load_matrix_sync(b1, sB + k0 * LDB + wx * 32 + 16, LDB);
        wmma::mma_sync(c0, a, b0, c0);
        wmma::mma_sync(c1, a, b1, c1);
    }
    __syncthreads();                      // all reads of sA/sB done
    wmma::store_matrix_sync(sOut + (wy * 16) * 68 + wx * 32, c0, 68, wmma::mem_row_major);
    wmma::store_matrix_sync(sOut + (wy * 16) * 68 + wx * 32 + 16, c1, 68, wmma::mem_row_major);
    __syncthreads();

    // Epilogue: thread (tx,ty) covers rows 4ty..4ty+3, cols 4tx..4tx+3.
    int tx = tid & 15, ty = tid >> 4;
    int h = tx >> 2;
    float alv[4], arv[4];
    #pragma unroll
    for (int c = 0; c < 4; c++) {
        int dcol = (tx & 3) * 4 + c;
        alv[c] = al[h * 16 + dcol];
        arv[c] = ar[h * 16 + dcol];
    }

    #pragma unroll
    for (int i = 0; i < 4; i++) {
        int n = base + 4 * ty + i;
        float4 v = *(const float4*)(sOut + (4 * ty + i) * 68 + 4 * tx);
        float pl = v.x * alv[0] + v.y * alv[1] + v.z * alv[2] + v.w * alv[3];
        float pr = v.x * arv[0] + v.y * arv[1] + v.z * arv[2] + v.w * arv[3];
        #pragma unroll
        for (int off = 1; off <= 2; off <<= 1) {
            pl += __shfl_xor_sync(0xffffffffu, pl, off);
            pr += __shfl_xor_sync(0xffffffffu, pr, off);
        }
        if (n < nN) {
            union { __half2 h2[2]; uint2 u; } pk;
            pk.h2[0] = __floats2half2_rn(v.x, v.y);
            pk.h2[1] = __floats2half2_rn(v.z, v.w);
            *(uint2*)(Hout + n * 64 + 4 * tx) = pk.u;
            if ((tx & 3) == 0) {
                El[n * 4 + h] = pl;
                Er[n * 4 + h] = pr;
            }
        }
    }
}

// ---------------------------------------------------------------------------
// Gather aggregation — 8 lanes per node, 4 nodes per warp (lane owns uint4 =
// 8 halfs of the 128B fp16 row). 4 independent node streams per warp give
// MLP=4 across nodes WITHOUT front-batching within a node (which regressed
// twice). ~45% fewer warp-iterations than 2-node/warp. fp32 accumulation;
// logits tiny -> unshifted softmax.
// MODE 0: relu(out+b) -> X16 (fp16). MODE 1: mean-head + log_softmax -> outf.
template<int MODE>
__global__ void __launch_bounds__(256)
aggregate(int nN, const int* __restrict__ rowptr, const int* __restrict__ csr,
          const float* __restrict__ el, const float* __restrict__ er,
          const __half* __restrict__ hfeat, const float* __restrict__ b,
          float* __restrict__ outf, __half* __restrict__ outh)
{
    int tid = threadIdx.x;
    int n = blockIdx.x * 32 + (tid >> 3);     // 32 nodes per 256-thread block
    bool valid = (n < nN);
    int nc = valid ? n : (nN - 1);
    int l = tid & 7;                          // lane-in-node 0..7
    int head = l >> 1;                        // cols 8l..8l+7 -> head = l>>1

    float erv = er[4 * nc + head];
    int p = rowptr[nc], pe = rowptr[nc + 1];

    float s = 0.f;
    float acc[8] = {};
    const uint4* hf = (const uint4*)hfeat;    // 8 uint4 per 64-half row

    while (p < pe) {
        int sn = csr[p];
        float e = el[4 * sn + head] + erv;
        uint4 u = hf[sn * 8 + l];
        e = (e > 0.f) ? e : 0.2f * e;
        float a = __expf(e);
        union { uint4 u; __half2 h2[4]; } pk; pk.u = u;
        s += a;
        #pragma unroll
        for (int q = 0; q < 4; q++) {
            float2 f = __half22float2(pk.h2[q]);
            acc[2 * q]     = fmaf(a, f.x, acc[2 * q]);
            acc[2 * q + 1] = fmaf(a, f.y, acc[2 * q + 1]);
        }
        p++;
    }

    float inv = (s > 0.f) ? 1.f / s : 0.f;
    int j0 = 8 * l;
    float v[8];
    #pragma unroll
    for (int q = 0; q < 8; q++) v[q] = fmaf(acc[q], inv, b[j0 + q]);

    if (MODE == 0) {
        if (valid) {
            union { __half2 h2[4]; uint4 u; } pk;
            #pragma unroll
            for (int q = 0; q < 4; q++)
                pk.h2[q] = __floats2half2_rn(fmaxf(v[2 * q], 0.f),
                                             fmaxf(v[2 * q + 1], 0.f));
            *(uint4*)(outh + 64 * n + j0) = pk.u;
        }
    } else {
        // head-sum: lanes sharing (l&1) across heads differ in bits 1,2 of l
        #pragma unroll
        for (int q = 0; q < 8; q++) {
            v[q] += __shfl_xor_sync(0xffffffffu, v[q], 2);
            v[q] += __shfl_xor_sync(0xffffffffu, v[q], 4);
            v[q] *= 0.25f;
        }
        // log-softmax over 16 classes: lane l&1==0 holds classes 0-7,
        // l&1==1 holds 8-15 (replicated over head positions)
        float mx = v[0];
        #pragma unroll
        for (int q = 1; q < 8; q++) mx = fmaxf(mx, v[q]);
        mx = fmaxf(mx, __shfl_xor_sync(0xffffffffu, mx, 1));
        float se = 0.f;
        #pragma unroll
        for (int q = 0; q < 8; q++) se += expf(v[q] - mx);
        se += __shfl_xor_sync(0xffffffffu, se, 1);
        float lse = mx + logf(se);
        if (valid && (l & 6) == 0) {          // lanes 0 and 1 of each node
            float4 o0 = make_float4(v[0] - lse, v[1] - lse, v[2] - lse, v[3] - lse);
            float4 o1 = make_float4(v[4] - lse, v[5] - lse, v[6] - lse, v[7] - lse);
            *(float4*)(outf + 16 * n + 8 * l)     = o0;
            *(float4*)(outf + 16 * n + 8 * l + 4) = o1;
        }
    }
}

// ---------------------------------------------------------------------------
extern "C" void kernel_launch(void* const* d_in, const int* in_sizes, int n_in,
                              void* d_out, int out_size)
{
    const float* feat = (const float*)d_in[0];
    const int*   src  = (const int*)d_in[1];
    const int*   dst  = (const int*)d_in[2];
    const float* W1   = (const float*)d_in[3];
    const float* al1  = (const float*)d_in[4];
    const float* ar1  = (const float*)d_in[5];
    const float* b1   = (const float*)d_in[6];
    const float* W2   = (const float*)d_in[7];
    const float* al2  = (const float*)d_in[8];
    const float* ar2  = (const float*)d_in[9];
    const float* b2   = (const float*)d_in[10];
    float* out = (float*)d_out;

    int nN = in_sizes[0] / 128;
    int nE = in_sizes[1];

    __half *p_h, *p_x16, *p_f16, *p_wt1, *p_wt2;
    float *p_el, *p_er;
    int *p_cnt, *p_rowptr, *p_csr;
    cudaGetSymbolAddress((void**)&p_h,     g_h);
    cudaGetSymbolAddress((void**)&p_x16,   g_x16);
    cudaGetSymbolAddress((void**)&p_f16,   g_f16);
    cudaGetSymbolAddress((void**)&p_wt1,   g_wt1);
    cudaGetSymbolAddress((void**)&p_wt2,   g_wt2);
    cudaGetSymbolAddress((void**)&p_el,    g_el);
    cudaGetSymbolAddress((void**)&p_er,    g_er);
    cudaGetSymbolAddress((void**)&p_cnt,   g_cnt);
    cudaGetSymbolAddress((void**)&p_rowptr,g_rowptr);
    cudaGetSymbolAddress((void**)&p_csr,   g_csr);

    const int TB = 256;
    int gEdge  = (nE + TB - 1) / TB;
    int gGemm  = (nN + 63) / 64;
    int gAgg   = (nN + 31) / 32;
    int gSetup = (nN * 64 + TB - 1) / TB;   // covers feat half2 count (largest)

    // Ordered so gemm_wmma<128> sits in the ncu -s 5 capture slot.
    setupT<<<gSetup, TB>>>(feat, W1, W2, (__half2*)p_f16, p_wt1, p_wt2, p_cnt, nN); // 0
    csr_count<<<gEdge, TB>>>(dst, nE, p_cnt);                                       // 1
    csr_scan<<<1, 1024>>>(nN, p_cnt, p_rowptr);                                     // 2
    gemm_wmma<128><<<gGemm, TB>>>(p_f16, p_wt1, al1, ar1, p_h, p_el, p_er, nN);     // 3
    csr_scatter<<<gEdge, TB>>>(src, dst, nE, p_rowptr, p_cnt, p_csr);               // 4

    aggregate<0><<<gAgg, TB>>>(nN, p_rowptr, p_csr, p_el, p_er, p_h, b1,
                               nullptr, p_x16);                                     // 5

    gemm_wmma<64><<<gGemm, TB>>>(p_x16, p_wt2, al2, ar2, p_h, p_el, p_er, nN);      // 6
    aggregate<1><<<gAgg, TB>>>(nN, p_rowptr, p_csr, p_el, p_er, p_h, b2,
                               out, nullptr);                                       // 7
}